// round 13
// baseline (speedup 1.0000x reference)
#include <cuda_runtime.h>
#include <cuda_bf16.h>
#include <math.h>

#define BB   256
#define OBSN 256
#define DIN  512
#define DDIM 1024
#define MMM  32
#define NSYN 64
#define NITR 4
#define NSYNCH 2080

// ---------------- fp32 scratch ----------------
__device__ float g_st[BB*MMM*DDIM];      // circular state trace [b][m][d]
__device__ float g_at[BB*MMM*DDIM];      // circular activated trace [b][m][d]
__device__ float g_tmp[4*BB*2048];       // GEMM split-K partial outputs
__device__ float g_r[NSYNCH];
__device__ float g_invden[NSYNCH];
__device__ unsigned char g_done[BB];

// ---------------- packed bf16-pair (hi/lo) operand buffers ----------------
__device__ __align__(16) unsigned g_obsH[256*128],  g_obsL[256*128];
__device__ __align__(16) unsigned g_fH[256*256],    g_fL[256*256];
__device__ __align__(16) unsigned g_hH[256*512],    g_hL[256*512];
__device__ __align__(16) unsigned g_atH[256*512],   g_atL[256*512];
__device__ __align__(16) unsigned g_w1H[1024*128],  g_w1L[1024*128];
__device__ __align__(16) unsigned g_w2H[1024*256],  g_w2L[1024*256];
__device__ __align__(16) unsigned g_s1H[2048*768],  g_s1L[2048*768];
__device__ __align__(16) unsigned g_s2H[2048*512],  g_s2L[2048*512];

// packed st trace for tensor-core nlm: [d][b][m] bf16 hi/lo
__device__ __align__(16) unsigned short g_stH16[1024*256*32];
__device__ __align__(16) unsigned short g_stL16[1024*256*32];
// nlm1 weights, 4 pre-rotated copies (rot rr => base rr+1): [rr][d][h][m_phys]
__device__ __align__(16) unsigned short g_w1rH[4][1024*1024];
__device__ __align__(16) unsigned short g_w1rL[4][1024*1024];

__device__ __forceinline__ float fsig(float x){ return __fdividef(1.f, 1.f + __expf(-x)); }

__device__ __forceinline__ unsigned pack2(__nv_bfloat16 a, __nv_bfloat16 b){
    return (unsigned)__bfloat16_as_ushort(a) | ((unsigned)__bfloat16_as_ushort(b) << 16);
}
__device__ __forceinline__ void split2(float x0, float x1, unsigned &hi, unsigned &lo){
    __nv_bfloat16 h0 = __float2bfloat16_rn(x0), h1 = __float2bfloat16_rn(x1);
    float r0 = x0 - __bfloat162float(h0);
    float r1 = x1 - __bfloat162float(h1);
    hi = pack2(h0, h1);
    lo = pack2(__float2bfloat16_rn(r0), __float2bfloat16_rn(r1));
}
__device__ __forceinline__ void split1(float x, unsigned short &hi, unsigned short &lo){
    __nv_bfloat16 h = __float2bfloat16_rn(x);
    float r = x - __bfloat162float(h);
    hi = __bfloat16_as_ushort(h);
    lo = __bfloat16_as_ushort(__float2bfloat16_rn(r));
}

// ---------------- mma / ldmatrix / cp.async primitives ----------------
__device__ __forceinline__ void mma16816(float* c, const unsigned* a, const unsigned* b){
    asm volatile("mma.sync.aligned.m16n8k16.row.col.f32.bf16.bf16.f32 "
        "{%0,%1,%2,%3},{%4,%5,%6,%7},{%8,%9},{%0,%1,%2,%3};"
        : "+f"(c[0]), "+f"(c[1]), "+f"(c[2]), "+f"(c[3])
        : "r"(a[0]), "r"(a[1]), "r"(a[2]), "r"(a[3]), "r"(b[0]), "r"(b[1]));
}
__device__ __forceinline__ void ldsm4(unsigned* r, unsigned saddr){
    asm volatile("ldmatrix.sync.aligned.m8n8.x4.shared.b16 {%0,%1,%2,%3}, [%4];"
        : "=r"(r[0]), "=r"(r[1]), "=r"(r[2]), "=r"(r[3]) : "r"(saddr));
}
__device__ __forceinline__ void cpasync16(unsigned sdst, const void* gsrc){
    asm volatile("cp.async.cg.shared.global [%0], [%1], 16;" :: "r"(sdst), "l"(gsrc));
}

// ---------------- fused prep: decode dones | synch prefactors | obs pack ----------------
__global__ void prep_kernel(const unsigned char* __restrict__ dones,
                            const float* __restrict__ dp,
                            const float* __restrict__ obs)
{
    int blk = blockIdx.x, t = threadIdx.x;
    if (blk == 0){
        __shared__ int has_gt1, has_off;
        if (t == 0){ has_gt1 = 0; has_off = 0; }
        __syncthreads();
        unsigned char v = dones[t];
        if (v > 1)             atomicOr(&has_gt1, 1);
        if (v != 0 && (t & 3)) atomicOr(&has_off, 1);
        __syncthreads();
        bool d;
        if (has_gt1)      d = ((const float*)dones)[t] != 0.0f;
        else if (has_off) d = dones[t] != 0;
        else              d = ((const int*)dones)[t] != 0;
        g_done[t] = d ? 1 : 0;
    } else if (blk <= 9){
        int p = (blk-1)*256 + t;
        if (p < NSYNCH){
            float c = fminf(fmaxf(dp[p], 0.f), 4.f);
            float r = __expf(-c);
            float den = 1.f, rp = 1.f;
            #pragma unroll
            for (int k=1;k<32;k++){ rp *= r; den += rp; }
            g_r[p] = r;
            g_invden[p] = rsqrtf(den);
        }
    } else {
        int i = (blk-10)*256 + t;
        if (i < BB*OBSN/2){
            unsigned h, l;
            split2(obs[2*i], obs[2*i+1], h, l);
            g_obsH[i] = h; g_obsL[i] = l;
        }
    }
}

// ---------------- init: reset + transpose; populate packed st + packed at-last ----------
__global__ __launch_bounds__(256) void init_state(
    const float* __restrict__ st_in, const float* __restrict__ at_in,
    const float* __restrict__ st0,   const float* __restrict__ at0)
{
    __shared__ float ts[32][33], ta[32][33];
    int b = blockIdx.y, d0 = blockIdx.x*32, t = threadIdx.x;
    bool rs = g_done[b] != 0;
    #pragma unroll
    for (int i=0;i<4;i++){
        int idx = t + i*256; int dd = idx >> 5, m = idx & 31;
        int gidx = (d0+dd)*MMM + m;
        ts[dd][m] = rs ? st0[gidx] : st_in[(size_t)b*DDIM*MMM + gidx];
        ta[dd][m] = rs ? at0[gidx] : at_in[(size_t)b*DDIM*MMM + gidx];
    }
    __syncthreads();
    #pragma unroll
    for (int i=0;i<4;i++){
        int idx = t + i*256; int m = idx >> 5, dd = idx & 31;
        size_t o = ((size_t)b*MMM + m)*DDIM + d0 + dd;
        float sv = ts[dd][m];
        g_st[o] = sv;
        g_at[o] = ta[dd][m];
        // packed st [d][b][m]
        unsigned short sh, sl;
        split1(sv, sh, sl);
        size_t po = (size_t)(d0+dd)*(256*32) + (size_t)b*32 + m;
        g_stH16[po] = sh;
        g_stL16[po] = sl;
        if (m == 31){
            float v = ta[dd][31];
            unsigned short hs, ls;
            split1(v, hs, ls);
            ((unsigned short*)g_atH)[(size_t)b*1024 + (d0+dd)] = hs;
            ((unsigned short*)g_atL)[(size_t)b*1024 + (d0+dd)] = ls;
        }
    }
}

// ---------------- weight transpose+convert, exact 1D grid ----------------
// ids: [0,256) w0 | [256,768) w1 | [768,3840) s1 | [3840,5888) s2 | [5888,6912) nlm1_w
__global__ __launch_bounds__(256) void conv_wt_all(
    const float* __restrict__ w0, const float* __restrict__ w1,
    const float* __restrict__ w2, const float* __restrict__ w3,
    const float* __restrict__ wn)
{
    int id = blockIdx.x;
    int t = threadIdx.x;
    if (id >= 5888){
        // nlm1_w (32 m, 32 h, 1024 d) -> 4 rotated copies [rr][d][h][m_phys]
        int local = id - 5888;
        int m = local >> 5, d0 = (local & 31)*32;
        #pragma unroll
        for (int i=0;i<4;i++){
            int e = t + i*256;            // 0..1023 = h*32+dd
            int h = e >> 5, dd = e & 31;
            float v = wn[((size_t)m*32 + h)*1024 + d0 + dd];
            unsigned short hi, lo;
            split1(v, hi, lo);
            #pragma unroll
            for (int rr=0; rr<4; rr++){
                int mp = (m + rr + 1) & 31;
                size_t o = (size_t)(d0+dd)*1024 + h*32 + mp;
                g_w1rH[rr][o] = hi;
                g_w1rL[rr][o] = lo;
            }
        }
        return;
    }
    __shared__ float sm[32][33];
    const float* W; unsigned *Th, *Tl; int K, N; int local;
    if (id < 256)      { W=w0; Th=g_w1H; Tl=g_w1L; K=256;  N=1024; local=id; }
    else if (id < 768) { W=w1; Th=g_w2H; Tl=g_w2L; K=512;  N=1024; local=id-256; }
    else if (id < 3840){ W=w2; Th=g_s1H; Tl=g_s1L; K=1536; N=2048; local=id-768; }
    else               { W=w3; Th=g_s2H; Tl=g_s2L; K=1024; N=2048; local=id-3840; }
    int tx = N >> 5;
    int k0 = (local / tx)*32, n0 = (local % tx)*32;
    int r = t >> 3, c = (t & 7)*4;
    float4 v = *(const float4*)(W + (size_t)(k0+r)*N + n0 + c);
    sm[r][c] = v.x; sm[r][c+1] = v.y; sm[r][c+2] = v.z; sm[r][c+3] = v.w;
    __syncthreads();
    int nr = t >> 3, kp2 = (t & 7)*2;
    int kk = kp2*2;
    unsigned h0,l0,h1,l1;
    split2(sm[kk][nr],   sm[kk+1][nr], h0, l0);
    split2(sm[kk+2][nr], sm[kk+3][nr], h1, l1);
    int KP = K >> 1;
    size_t o = (size_t)(n0+nr)*KP + (k0>>1) + kp2;
    Th[o] = h0; Th[o+1] = h1;
    Tl[o] = l0; Tl[o+1] = l1;
}

// ---------------- 3xBF16 tensor GEMM, split-K, 64x64 tile, 256 thr, 3-stage --------------
#define GKP 12
__global__ __launch_bounds__(256) void gemm_bf16p(
    const unsigned* __restrict__ A1h, const unsigned* __restrict__ A1l, int lda1,
    const unsigned* __restrict__ A2h, const unsigned* __restrict__ A2l, int lda2, int KP1,
    const unsigned* __restrict__ Bh,  const unsigned* __restrict__ Bl,  int ldb,
    const float* __restrict__ bias, float* __restrict__ C, int N, int KPsplit)
{
    __shared__ unsigned As[3][2][64][GKP];
    __shared__ unsigned Bs[3][2][64][GKP];
    int tid = threadIdx.x;
    int m0 = blockIdx.y*64, n0 = blockIdx.x*64;
    int kbase = blockIdx.z * KPsplit;
    unsigned aBase = (unsigned)__cvta_generic_to_shared(&As[0][0][0][0]);
    unsigned bBase = (unsigned)__cvta_generic_to_shared(&Bs[0][0][0][0]);

    bool isB = tid >= 128;
    int lt = tid & 127;
    int lrow = lt >> 1, lch = lt & 1;
    int KT = KPsplit >> 3;

    int wid = tid >> 5, lane = tid & 31;
    int wm = wid >> 2, wn = wid & 3;
    int arow = wm*32 + (lane & 7) + (lane & 8);
    int akp  = (lane & 16) ? 4 : 0;
    int brow = wn*16 + (lane & 7) + ((lane & 16) ? 8 : 0);
    int bkp  = (lane & 8) ? 4 : 0;
    unsigned aOff0 = ((unsigned)(arow     *GKP + akp))*4u;
    unsigned aOff1 = ((unsigned)((arow+16)*GKP + akp))*4u;
    unsigned bOff  = ((unsigned)(brow     *GKP + bkp))*4u;

    float acc[2][2][4];
    #pragma unroll
    for (int a=0;a<2;a++)
        #pragma unroll
        for (int b=0;b<2;b++)
            #pragma unroll
            for (int c=0;c<4;c++) acc[a][b][c]=0.f;

    auto issue = [&](int kt){
        if (kt < KT){
            int st = kt % 3;
            int kp0 = kbase + kt*8 + lch*4;
            unsigned dh = (((unsigned)(st*2+0)*64 + lrow)*GKP + lch*4)*4u;
            unsigned dl = (((unsigned)(st*2+1)*64 + lrow)*GKP + lch*4)*4u;
            if (!isB){
                const unsigned *sh_, *sl_;
                if (kp0 < KP1){
                    size_t o = (size_t)(m0+lrow)*lda1 + kp0;
                    sh_ = A1h + o; sl_ = A1l + o;
                } else {
                    size_t o = (size_t)(m0+lrow)*lda2 + (kp0 - KP1);
                    sh_ = A2h + o; sl_ = A2l + o;
                }
                cpasync16(aBase + dh, sh_);
                cpasync16(aBase + dl, sl_);
            } else {
                size_t o = (size_t)(n0+lrow)*ldb + kp0;
                cpasync16(bBase + dh, Bh + o);
                cpasync16(bBase + dl, Bl + o);
            }
        }
        asm volatile("cp.async.commit_group;" ::: "memory");
    };

    issue(0); issue(1);

    for (int kt = 0; kt < KT; kt++){
        asm volatile("cp.async.wait_group 1;" ::: "memory");
        __syncthreads();
        int st = kt % 3;
        unsigned sa = aBase + (unsigned)st*(2*64*GKP*4);
        unsigned sb = bBase + (unsigned)st*(2*64*GKP*4);
        unsigned ah0[4], ah1[4], al0[4], al1[4], bh[4], bl[4];
        ldsm4(ah0, sa + aOff0);
        ldsm4(ah1, sa + aOff1);
        ldsm4(al0, sa + (64*GKP*4) + aOff0);
        ldsm4(al1, sa + (64*GKP*4) + aOff1);
        ldsm4(bh,  sb + bOff);
        ldsm4(bl,  sb + (64*GKP*4) + bOff);

        mma16816(acc[0][0], ah0, bh+0);
        mma16816(acc[0][1], ah0, bh+2);
        mma16816(acc[1][0], ah1, bh+0);
        mma16816(acc[1][1], ah1, bh+2);
        mma16816(acc[0][0], ah0, bl+0);
        mma16816(acc[0][1], ah0, bl+2);
        mma16816(acc[1][0], ah1, bl+0);
        mma16816(acc[1][1], ah1, bl+2);
        mma16816(acc[0][0], al0, bh+0);
        mma16816(acc[0][1], al0, bh+2);
        mma16816(acc[1][0], al1, bh+0);
        mma16816(acc[1][1], al1, bh+2);

        issue(kt+2);
    }

    float* Cz = C + (size_t)blockIdx.z * (size_t)BB * (size_t)N;
    int g = lane >> 2, t4 = lane & 3;
    bool addb = (blockIdx.z == 0);
    #pragma unroll
    for (int mt=0;mt<2;mt++){
        #pragma unroll
        for (int nt=0;nt<2;nt++){
            int row = m0 + wm*32 + mt*16 + g;
            int col = n0 + wn*16 + nt*8 + 2*t4;
            float bx = addb ? __ldg(bias + col)     : 0.f;
            float by = addb ? __ldg(bias + col + 1) : 0.f;
            float2 v0 = make_float2(acc[mt][nt][0]+bx, acc[mt][nt][1]+by);
            float2 v1 = make_float2(acc[mt][nt][2]+bx, acc[mt][nt][3]+by);
            *(float2*)&Cz[(size_t)row*N + col]     = v0;
            *(float2*)&Cz[(size_t)(row+8)*N + col] = v1;
        }
    }
}

// ---------------- GLU + LayerNorm (sums nparts split-K partials) -> packed bf16 hi/lo ------
__global__ __launch_bounds__(256) void glu_ln_pack(
    const float* __restrict__ X, const float* __restrict__ gamma,
    const float* __restrict__ beta, unsigned* __restrict__ outH,
    unsigned* __restrict__ outL, int N, int nparts)
{
    __shared__ float sg[1024];
    __shared__ float red[18];
    int b = blockIdx.x, t = threadIdx.x;
    size_t zstride = (size_t)BB*2*N;
    const float* xr = X + (size_t)b*2*N;
    int N4 = N >> 2;
    float s1=0.f, s2=0.f;
    for (int p=t; p<N4; p+=256){
        float4 a = *(const float4*)(xr + 4*p);
        float4 c = *(const float4*)(xr + N + 4*p);
        for (int z=1; z<nparts; z++){
            float4 a2 = *(const float4*)(xr + z*zstride + 4*p);
            float4 c2 = *(const float4*)(xr + z*zstride + N + 4*p);
            a.x+=a2.x; a.y+=a2.y; a.z+=a2.z; a.w+=a2.w;
            c.x+=c2.x; c.y+=c2.y; c.z+=c2.z; c.w+=c2.w;
        }
        float g0 = a.x*fsig(c.x), g1 = a.y*fsig(c.y);
        float g2 = a.z*fsig(c.z), g3 = a.w*fsig(c.w);
        *(float4*)&sg[4*p] = make_float4(g0,g1,g2,g3);
        s1 += (g0+g1)+(g2+g3);
        s2 += (g0*g0+g1*g1)+(g2*g2+g3*g3);
    }
    #pragma unroll
    for (int o=16;o;o>>=1){ s1+=__shfl_xor_sync(0xffffffffu,s1,o); s2+=__shfl_xor_sync(0xffffffffu,s2,o); }
    if ((t&31)==0){ red[t>>5]=s1; red[8+(t>>5)]=s2; }
    __syncthreads();
    if (t==0){
        float a=0.f,c=0.f;
        for (int i=0;i<8;i++){ a+=red[i]; c+=red[8+i]; }
        red[16]=a; red[17]=c;
    }
    __syncthreads();
    float mu  = red[16]/(float)N;
    float var = red[17]/(float)N - mu*mu;
    float inv = rsqrtf(var + 1e-6f);
    int NP = N >> 1;
    for (int p=t; p<N4; p+=256){
        int j = 4*p;
        float4 gm = *(const float4*)(gamma + j);
        float4 bt = *(const float4*)(beta + j);
        float4 gv = *(const float4*)&sg[j];
        float y0 = (gv.x-mu)*inv*gm.x + bt.x;
        float y1 = (gv.y-mu)*inv*gm.y + bt.y;
        float y2 = (gv.z-mu)*inv*gm.z + bt.z;
        float y3 = (gv.w-mu)*inv*gm.w + bt.w;
        unsigned h0,l0,h1,l1;
        split2(y0,y1,h0,l0);
        split2(y2,y3,h1,l1);
        size_t o = (size_t)b*NP + 2*p;
        *(uint2*)&outH[o] = make_uint2(h0,h1);
        *(uint2*)&outL[o] = make_uint2(l0,l1);
    }
}

// ---------------- GLU + LayerNorm (sums partials) -> fp32 st slot + packed st slot --------
__global__ __launch_bounds__(256) void glu_ln_f32(
    const float* __restrict__ X, const float* __restrict__ gamma,
    const float* __restrict__ beta, float* __restrict__ outp,
    int N, int ostride, int nparts, int slot)
{
    __shared__ float sg[1024];
    __shared__ float red[18];
    int b = blockIdx.x, t = threadIdx.x;
    size_t zstride = (size_t)BB*2*N;
    const float* xr = X + (size_t)b*2*N;
    int N4 = N >> 2;
    float s1=0.f, s2=0.f;
    for (int p=t; p<N4; p+=256){
        float4 a = *(const float4*)(xr + 4*p);
        float4 c = *(const float4*)(xr + N + 4*p);
        for (int z=1; z<nparts; z++){
            float4 a2 = *(const float4*)(xr + z*zstride + 4*p);
            float4 c2 = *(const float4*)(xr + z*zstride + N + 4*p);
            a.x+=a2.x; a.y+=a2.y; a.z+=a2.z; a.w+=a2.w;
            c.x+=c2.x; c.y+=c2.y; c.z+=c2.z; c.w+=c2.w;
        }
        float g0 = a.x*fsig(c.x), g1 = a.y*fsig(c.y);
        float g2 = a.z*fsig(c.z), g3 = a.w*fsig(c.w);
        *(float4*)&sg[4*p] = make_float4(g0,g1,g2,g3);
        s1 += (g0+g1)+(g2+g3);
        s2 += (g0*g0+g1*g1)+(g2*g2+g3*g3);
    }
    #pragma unroll
    for (int o=16;o;o>>=1){ s1+=__shfl_xor_sync(0xffffffffu,s1,o); s2+=__shfl_xor_sync(0xffffffffu,s2,o); }
    if ((t&31)==0){ red[t>>5]=s1; red[8+(t>>5)]=s2; }
    __syncthreads();
    if (t==0){
        float a=0.f,c=0.f;
        for (int i=0;i<8;i++){ a+=red[i]; c+=red[8+i]; }
        red[16]=a; red[17]=c;
    }
    __syncthreads();
    float mu  = red[16]/(float)N;
    float var = red[17]/(float)N - mu*mu;
    float inv = rsqrtf(var + 1e-6f);
    for (int p=t; p<N4; p+=256){
        int j = 4*p;
        float4 gm = *(const float4*)(gamma + j);
        float4 bt = *(const float4*)(beta + j);
        float4 gv = *(const float4*)&sg[j];
        float4 y;
        y.x = (gv.x-mu)*inv*gm.x + bt.x;
        y.y = (gv.y-mu)*inv*gm.y + bt.y;
        y.z = (gv.z-mu)*inv*gm.z + bt.z;
        y.w = (gv.w-mu)*inv*gm.w + bt.w;
        *(float4*)&outp[(size_t)b*ostride + j] = y;
        // packed st slot write [d][b][m=slot]
        #pragma unroll
        for (int q=0;q<4;q++){
            float v = (&y.x)[q];
            unsigned short hh, ll;
            split1(v, hh, ll);
            size_t po = (size_t)(j+q)*(256*32) + (size_t)b*32 + slot;
            g_stH16[po] = hh;
            g_stL16[po] = ll;
        }
    }
}

// ---------------- tensor-core NLM: per-d GEMM [128b x 32m] @ [32m x 32h] -----------------
// grid (2 b-blocks, 1024 d), 256 thr = 8 warps; it = iteration (rotation rr = it, slot = it)
__global__ __launch_bounds__(256) void nlm_tc(
    const float* __restrict__ b1, const float* __restrict__ T1,
    const float* __restrict__ w2, const float* __restrict__ b2, const float* __restrict__ T2,
    int it)
{
    __shared__ __align__(16) unsigned char sA[2][128*80];
    __shared__ __align__(16) unsigned char sW[2][32*80];
    __shared__ float B1s[32];
    __shared__ float W2s[32];
    __shared__ float B2s[2];
    __shared__ float Ts[2];

    int t = threadIdx.x;
    int b0 = blockIdx.x * 128;
    int d  = blockIdx.y;
    int slot = it;

    // stage A (packed st [d][b][m], 64B rows -> 80B-stride smem rows)
    {
        int r = t >> 1, half = t & 1;
        size_t srcoff = ((size_t)d*256 + b0 + r)*64 + (size_t)half*32;
        const uint4* sh = (const uint4*)((const char*)g_stH16 + srcoff);
        const uint4* sl = (const uint4*)((const char*)g_stL16 + srcoff);
        uint4* dh = (uint4*)(sA[0] + r*80 + half*32);
        uint4* dl = (uint4*)(sA[1] + r*80 + half*32);
        dh[0] = sh[0]; dh[1] = sh[1];
        dl[0] = sl[0]; dl[1] = sl[1];
    }
    // stage W (pre-rotated copy it): 2 arrays x 2KB dense -> 80B-stride rows
    {
        int hl = t >> 7, tt = t & 127;
        int r = tt >> 2, part = (tt & 3)*16;
        const char* src = (const char*)(hl ? g_w1rL[it] : g_w1rH[it]) + (size_t)d*2048 + r*64 + part;
        *(uint4*)(sW[hl] + r*80 + part) = *(const uint4*)src;
    }
    if (t < 32)      B1s[t] = b1[d*32 + t];
    else if (t < 64) W2s[t-32] = w2[(t-32)*1024 + d];
    else if (t == 64){ B2s[0] = b2[d*2]; B2s[1] = b2[d*2+1];
                       Ts[0] = 1.f/T1[0]; Ts[1] = 1.f/T2[0]; }
    __syncthreads();

    int wid = t >> 5, lane = t & 31;
    unsigned a0Base = (unsigned)__cvta_generic_to_shared(sA[0]);
    unsigned a1Base = (unsigned)__cvta_generic_to_shared(sA[1]);
    unsigned w0Base = (unsigned)__cvta_generic_to_shared(sW[0]);
    unsigned w1Base = (unsigned)__cvta_generic_to_shared(sW[1]);
    unsigned aOff = (unsigned)((wid*16 + (lane & 15))*80 + (lane >> 4)*16);
    unsigned bOff = (unsigned)((((lane & 7) + ((lane & 16) ? 8 : 0))*80) + ((lane & 8) ? 16 : 0));

    float acc[4][4];
    #pragma unroll
    for (int i=0;i<4;i++)
        #pragma unroll
        for (int j=0;j<4;j++) acc[i][j]=0.f;

    #pragma unroll
    for (int ks=0; ks<2; ks++){
        unsigned kb = ks*32;
        unsigned aH[4], aL[4], bh0[4], bh1[4], bl0[4], bl1[4];
        ldsm4(aH, a0Base + aOff + kb);
        ldsm4(aL, a1Base + aOff + kb);
        ldsm4(bh0, w0Base + bOff + kb);
        ldsm4(bh1, w0Base + bOff + 16*80 + kb);
        ldsm4(bl0, w1Base + bOff + kb);
        ldsm4(bl1, w1Base + bOff + 16*80 + kb);
        mma16816(acc[0], aH, bh0+0);
        mma16816(acc[1], aH, bh0+2);
        mma16816(acc[2], aH, bh1+0);
        mma16816(acc[3], aH, bh1+2);
        mma16816(acc[0], aH, bl0+0);
        mma16816(acc[1], aH, bl0+2);
        mma16816(acc[2], aH, bl1+0);
        mma16816(acc[3], aH, bl1+2);
        mma16816(acc[0], aL, bh0+0);
        mma16816(acc[1], aL, bh0+2);
        mma16816(acc[2], aL, bh1+0);
        mma16816(acc[3], aL, bh1+2);
    }

    int g = lane >> 2, t4 = lane & 3;
    float invT1 = Ts[0], invT2 = Ts[1];
    #pragma unroll
    for (int nt=0; nt<4; nt++)
        #pragma unroll
        for (int c=0; c<4; c++){
            int h = nt*8 + 2*t4 + (c & 1);
            acc[nt][c] = (acc[nt][c] + B1s[h]) * invT1;
        }
    float y0[2], y1[2];
    #pragma unroll
    for (int r=0; r<2; r++){
        y0[r]=0.f; y1[r]=0.f;
        #pragma unroll
        for (int nt=0; nt<2; nt++)
            #pragma unroll
            for (int e=0; e<2; e++){
                int c = r*2+e;
                float gl = acc[nt][c] * fsig(acc[nt+2][c]);
                int hp = nt*8 + 2*t4 + e;
                y0[r] += gl * W2s[hp*2+0];
                y1[r] += gl * W2s[hp*2+1];
            }
    }
    #pragma unroll
    for (int off=1; off<4; off<<=1){
        y0[0] += __shfl_xor_sync(0xffffffffu, y0[0], off);
        y1[0] += __shfl_xor_sync(0xffffffffu, y1[0], off);
        y0[1] += __shfl_xor_sync(0xffffffffu, y0[1], off);
        y1[1] += __shfl_xor_sync(0xffffffffu, y1[1], off);
    }
    if (t4 == 0){
        #pragma unroll
        for (int r=0; r<2; r++){
            float ya = (y0[r] + B2s[0]) * invT2;
            float yb = (y1[r] + B2s[1]) * invT2;
            float outv = ya * fsig(yb);
            int bg = b0 + wid*16 + g + r*8;
            g_at[((size_t)bg*MMM + slot)*DDIM + d] = outv;
            unsigned short hh, ll;
            split1(outv, hh, ll);
            ((unsigned short*)g_atH)[(size_t)bg*1024 + d] = hh;
            ((unsigned short*)g_atL)[(size_t)bg*1024 + d] = ll;
        }
    }
}

// ---------------- synchronization output (Horner) ----------------
__global__ __launch_bounds__(256) void synch_kernel(float* __restrict__ outp, int base)
{
    __shared__ float S[32][64];
    int b = blockIdx.x, t = threadIdx.x;
    #pragma unroll
    for (int i=0;i<8;i++){
        int idx = t + i*256; int m = idx >> 6, n = idx & 63;
        S[m][n] = g_at[((size_t)b*MMM + ((base+m)&31))*DDIM + (DDIM-NSYN) + n];
    }
    __syncthreads();
    for (int p=t; p<NSYNCH; p+=256){
        int i=0, off=0;
        while (p >= off + (NSYN - i)){ off += NSYN - i; ++i; }
        int j = i + (p - off);
        float r = g_r[p];
        float num = 0.f;
        #pragma unroll
        for (int m=0;m<32;m++)
            num = num*r + S[m][i]*S[m][j];
        outp[(size_t)b*NSYNCH + p] = num * g_invden[p];
    }
}

// ---------------- final transpose [b][m][d] -> (B,D,M) ----------------
__global__ void transpose_out(float* __restrict__ outp, int base)
{
    __shared__ float tile[32][33];
    const float* src = blockIdx.z ? g_at : g_st;
    float* dst = outp + (size_t)blockIdx.z * (size_t)BB*DDIM*MMM;
    int b = blockIdx.y, d0 = blockIdx.x*32, t = threadIdx.x;
    #pragma unroll
    for (int i=0;i<4;i++){
        int idx = t + i*256; int m = idx >> 5, dd = idx & 31;
        tile[m][dd] = src[((size_t)b*MMM + ((base+m)&31))*DDIM + d0 + dd];
    }
    __syncthreads();
    #pragma unroll
    for (int i=0;i<4;i++){
        int idx = t + i*256; int dd = idx >> 5, m = idx & 31;
        dst[((size_t)b*DDIM + d0 + dd)*MMM + m] = tile[m][dd];
    }
}

// ---------------- host launch ----------------
extern "C" void kernel_launch(void* const* d_in, const int* in_sizes, int n_in,
                              void* d_out, int out_size)
{
    const float* obs          = (const float*)d_in[0];
    const unsigned char* dones= (const unsigned char*)d_in[1];
    const float* state_trace  = (const float*)d_in[3];
    const float* at_trace     = (const float*)d_in[4];
    const float* start_trace  = (const float*)d_in[5];
    const float* start_at     = (const float*)d_in[6];
    const float* bb_w1  = (const float*)d_in[7];
    const float* bb_b1  = (const float*)d_in[8];
    const float* bb_l1s = (const float*)d_in[9];
    const float* bb_l1b = (const float*)d_in[10];
    const float* bb_w2  = (const float*)d_in[11];
    const float* bb_b2  = (const float*)d_in[12];
    const float* bb_l2s = (const float*)d_in[13];
    const float* bb_l2b = (const float*)d_in[14];
    const float* syn_w1 = (const float*)d_in[15];
    const float* syn_b1 = (const float*)d_in[16];
    const float* syn_l1s= (const float*)d_in[17];
    const float* syn_l1b= (const float*)d_in[18];
    const float* syn_w2 = (const float*)d_in[19];
    const float* syn_b2 = (const float*)d_in[20];
    const float* syn_l2s= (const float*)d_in[21];
    const float* syn_l2b= (const float*)d_in[22];
    const float* nlm1_w = (const float*)d_in[23];
    const float* nlm1_b = (const float*)d_in[24];
    const float* nlm1_T = (const float*)d_in[25];
    const float* nlm2_w = (const float*)d_in[26];
    const float* nlm2_b = (const float*)d_in[27];
    const float* nlm2_T = (const float*)d_in[28];
    const float* decayp = (const float*)d_in[29];
    float* outp = (float*)d_out;

    float *p_tmp, *p_st;
    unsigned *p_obsH,*p_obsL,*p_fH,*p_fL,*p_hH,*p_hL,*p_atH,*p_atL;
    unsigned *p_w1H,*p_w1L,*p_w2H,*p_w2L,*p_s1H,*p_s1L,*p_s2H,*p_s2L;
    cudaGetSymbolAddress((void**)&p_tmp, g_tmp);
    cudaGetSymbolAddress((void**)&p_st,  g_st);
    cudaGetSymbolAddress((void**)&p_obsH, g_obsH); cudaGetSymbolAddress((void**)&p_obsL, g_obsL);
    cudaGetSymbolAddress((void**)&p_fH,   g_fH);   cudaGetSymbolAddress((void**)&p_fL,   g_fL);
    cudaGetSymbolAddress((void**)&p_hH,   g_hH);   cudaGetSymbolAddress((void**)&p_hL,   g_hL);
    cudaGetSymbolAddress((void**)&p_atH,  g_atH);  cudaGetSymbolAddress((void**)&p_atL,  g_atL);
    cudaGetSymbolAddress((void**)&p_w1H,  g_w1H);  cudaGetSymbolAddress((void**)&p_w1L,  g_w1L);
    cudaGetSymbolAddress((void**)&p_w2H,  g_w2H);  cudaGetSymbolAddress((void**)&p_w2L,  g_w2L);
    cudaGetSymbolAddress((void**)&p_s1H,  g_s1H);  cudaGetSymbolAddress((void**)&p_s1L,  g_s1L);
    cudaGetSymbolAddress((void**)&p_s2H,  g_s2H);  cudaGetSymbolAddress((void**)&p_s2L,  g_s2L);

    // 1) fused prep, state relayout (+packed st/at), weight conversion (+nlm1 rotations)
    prep_kernel<<<138, 256>>>(dones, decayp, obs);
    init_state<<<dim3(DDIM/32, BB), 256>>>(state_trace, at_trace, start_trace, start_at);
    conv_wt_all<<<6912, 256>>>(bb_w1, bb_w2, syn_w1, syn_w2, nlm1_w);

    // 2) backbone (split-K=2)
    gemm_bf16p<<<dim3(16, 4, 2), 256>>>(p_obsH, p_obsL, 128,
                                        p_obsH, p_obsL, 128, 128,
                                        p_w1H, p_w1L, 128,
                                        bb_b1, p_tmp, 1024, 64);
    glu_ln_pack<<<BB, 256>>>(p_tmp, bb_l1s, bb_l1b, p_fH, p_fL, DIN, 2);
    gemm_bf16p<<<dim3(16, 4, 2), 256>>>(p_fH, p_fL, 256,
                                        p_fH, p_fL, 256, 256,
                                        p_w2H, p_w2L, 256,
                                        bb_b2, p_tmp, 1024, 128);
    glu_ln_pack<<<BB, 256>>>(p_tmp, bb_l2s, bb_l2b, p_fH, p_fL, DIN, 2);

    // 3) recurrent iterations (split-K=4 on syn GEMMs, tensor-core NLM)
    for (int t = 0; t < NITR; t++){
        gemm_bf16p<<<dim3(32, 4, 4), 256>>>(p_fH, p_fL, 256,
                                            p_atH, p_atL, 512, 256,
                                            p_s1H, p_s1L, 768,
                                            syn_b1, p_tmp, 2048, 192);
        glu_ln_pack<<<BB, 256>>>(p_tmp, syn_l1s, syn_l1b, p_hH, p_hL, DDIM, 4);
        gemm_bf16p<<<dim3(32, 4, 4), 256>>>(p_hH, p_hL, 512,
                                            p_hH, p_hL, 512, 512,
                                            p_s2H, p_s2L, 512,
                                            syn_b2, p_tmp, 2048, 128);
        glu_ln_f32<<<BB, 256>>>(p_tmp, syn_l2s, syn_l2b, p_st + (size_t)t*DDIM,
                                DDIM, MMM*DDIM, 4, t);
        nlm_tc<<<dim3(2, 1024), 256>>>(nlm1_b, nlm1_T, nlm2_w, nlm2_b, nlm2_T, t);
    }

    // 4) outputs
    synch_kernel<<<BB, 256>>>(outp + (size_t)2*BB*DDIM*MMM, NITR & 31);
    transpose_out<<<dim3(DDIM/32, BB, 2), 256>>>(outp, NITR & 31);
}

// round 15
// speedup vs baseline: 1.0764x; 1.0764x over previous
#include <cuda_runtime.h>
#include <cuda_bf16.h>
#include <math.h>

#define BB   256
#define OBSN 256
#define DIN  512
#define DDIM 1024
#define MMM  32
#define NSYN 64
#define NITR 4
#define NSYNCH 2080

// ---------------- fp32 scratch ----------------
__device__ float g_st[BB*MMM*DDIM];      // circular state trace [b][m][d]
__device__ float g_at[BB*MMM*DDIM];      // circular activated trace [b][m][d]
__device__ float g_tmp[4*BB*2048];       // GEMM split-K partial outputs
__device__ float g_r[NSYNCH];
__device__ float g_invden[NSYNCH];
__device__ unsigned char g_done[BB];

// ---------------- packed bf16-pair (hi/lo) operand buffers ----------------
__device__ __align__(16) unsigned g_obsH[256*128],  g_obsL[256*128];
__device__ __align__(16) unsigned g_fH[256*256],    g_fL[256*256];
__device__ __align__(16) unsigned g_hH[256*512],    g_hL[256*512];
__device__ __align__(16) unsigned g_atH[256*512],   g_atL[256*512];
__device__ __align__(16) unsigned g_w1H[1024*128],  g_w1L[1024*128];
__device__ __align__(16) unsigned g_w2H[1024*256],  g_w2L[1024*256];
__device__ __align__(16) unsigned g_s1H[2048*768],  g_s1L[2048*768];
__device__ __align__(16) unsigned g_s2H[2048*512],  g_s2L[2048*512];

// packed st trace for tensor-core nlm: [d][b][m] bf16 hi/lo
__device__ __align__(16) unsigned short g_stH16[1024*256*32];
__device__ __align__(16) unsigned short g_stL16[1024*256*32];
// nlm1 weights, 4 pre-rotated copies (rot rr => base rr+1): [rr][d][h][m_phys]
__device__ __align__(16) unsigned short g_w1rH[4][1024*1024];
__device__ __align__(16) unsigned short g_w1rL[4][1024*1024];

__device__ __forceinline__ float fsig(float x){ return __fdividef(1.f, 1.f + __expf(-x)); }

__device__ __forceinline__ unsigned pack2(__nv_bfloat16 a, __nv_bfloat16 b){
    return (unsigned)__bfloat16_as_ushort(a) | ((unsigned)__bfloat16_as_ushort(b) << 16);
}
__device__ __forceinline__ void split2(float x0, float x1, unsigned &hi, unsigned &lo){
    __nv_bfloat16 h0 = __float2bfloat16_rn(x0), h1 = __float2bfloat16_rn(x1);
    float r0 = x0 - __bfloat162float(h0);
    float r1 = x1 - __bfloat162float(h1);
    hi = pack2(h0, h1);
    lo = pack2(__float2bfloat16_rn(r0), __float2bfloat16_rn(r1));
}
__device__ __forceinline__ void split1(float x, unsigned short &hi, unsigned short &lo){
    __nv_bfloat16 h = __float2bfloat16_rn(x);
    float r = x - __bfloat162float(h);
    hi = __bfloat16_as_ushort(h);
    lo = __bfloat16_as_ushort(__float2bfloat16_rn(r));
}

// ---------------- mma / ldmatrix / cp.async primitives ----------------
__device__ __forceinline__ void mma16816(float* c, const unsigned* a, const unsigned* b){
    asm volatile("mma.sync.aligned.m16n8k16.row.col.f32.bf16.bf16.f32 "
        "{%0,%1,%2,%3},{%4,%5,%6,%7},{%8,%9},{%0,%1,%2,%3};"
        : "+f"(c[0]), "+f"(c[1]), "+f"(c[2]), "+f"(c[3])
        : "r"(a[0]), "r"(a[1]), "r"(a[2]), "r"(a[3]), "r"(b[0]), "r"(b[1]));
}
__device__ __forceinline__ void ldsm4(unsigned* r, unsigned saddr){
    asm volatile("ldmatrix.sync.aligned.m8n8.x4.shared.b16 {%0,%1,%2,%3}, [%4];"
        : "=r"(r[0]), "=r"(r[1]), "=r"(r[2]), "=r"(r[3]) : "r"(saddr));
}
__device__ __forceinline__ void cpasync16(unsigned sdst, const void* gsrc){
    asm volatile("cp.async.cg.shared.global [%0], [%1], 16;" :: "r"(sdst), "l"(gsrc));
}

// ---------------- fused prep: decode dones | synch prefactors | obs pack ----------------
__global__ void prep_kernel(const unsigned char* __restrict__ dones,
                            const float* __restrict__ dp,
                            const float* __restrict__ obs)
{
    int blk = blockIdx.x, t = threadIdx.x;
    if (blk == 0){
        __shared__ int has_gt1, has_off;
        if (t == 0){ has_gt1 = 0; has_off = 0; }
        __syncthreads();
        unsigned char v = dones[t];
        if (v > 1)             atomicOr(&has_gt1, 1);
        if (v != 0 && (t & 3)) atomicOr(&has_off, 1);
        __syncthreads();
        bool d;
        if (has_gt1)      d = ((const float*)dones)[t] != 0.0f;
        else if (has_off) d = dones[t] != 0;
        else              d = ((const int*)dones)[t] != 0;
        g_done[t] = d ? 1 : 0;
    } else if (blk <= 9){
        int p = (blk-1)*256 + t;
        if (p < NSYNCH){
            float c = fminf(fmaxf(dp[p], 0.f), 4.f);
            float r = __expf(-c);
            float den = 1.f, rp = 1.f;
            #pragma unroll
            for (int k=1;k<32;k++){ rp *= r; den += rp; }
            g_r[p] = r;
            g_invden[p] = rsqrtf(den);
        }
    } else {
        int i = (blk-10)*256 + t;
        if (i < BB*OBSN/2){
            unsigned h, l;
            split2(obs[2*i], obs[2*i+1], h, l);
            g_obsH[i] = h; g_obsL[i] = l;
        }
    }
}

// ---------------- init: reset + transpose; populate packed st + packed at-last ----------
__global__ __launch_bounds__(256) void init_state(
    const float* __restrict__ st_in, const float* __restrict__ at_in,
    const float* __restrict__ st0,   const float* __restrict__ at0)
{
    __shared__ float ts[32][33], ta[32][33];
    int b = blockIdx.y, d0 = blockIdx.x*32, t = threadIdx.x;
    bool rs = g_done[b] != 0;
    #pragma unroll
    for (int i=0;i<4;i++){
        int idx = t + i*256; int dd = idx >> 5, m = idx & 31;
        int gidx = (d0+dd)*MMM + m;
        ts[dd][m] = rs ? st0[gidx] : st_in[(size_t)b*DDIM*MMM + gidx];
        ta[dd][m] = rs ? at0[gidx] : at_in[(size_t)b*DDIM*MMM + gidx];
    }
    __syncthreads();
    #pragma unroll
    for (int i=0;i<4;i++){
        int idx = t + i*256; int m = idx >> 5, dd = idx & 31;
        size_t o = ((size_t)b*MMM + m)*DDIM + d0 + dd;
        float sv = ts[dd][m];
        g_st[o] = sv;
        g_at[o] = ta[dd][m];
        unsigned short sh, sl;
        split1(sv, sh, sl);
        size_t po = (size_t)(d0+dd)*(256*32) + (size_t)b*32 + m;
        g_stH16[po] = sh;
        g_stL16[po] = sl;
        if (m == 31){
            float v = ta[dd][31];
            unsigned short hs, ls;
            split1(v, hs, ls);
            ((unsigned short*)g_atH)[(size_t)b*1024 + (d0+dd)] = hs;
            ((unsigned short*)g_atL)[(size_t)b*1024 + (d0+dd)] = ls;
        }
    }
}

// ---------------- weight transpose+convert, exact 1D grid ----------------
// ids: [0,256) w0 | [256,768) w1 | [768,3840) s1 | [3840,5888) s2 | [5888,6016) nlm1_w
__global__ __launch_bounds__(256) void conv_wt_all(
    const float* __restrict__ w0, const float* __restrict__ w1,
    const float* __restrict__ w2, const float* __restrict__ w3,
    const float* __restrict__ wn)
{
    int id = blockIdx.x;
    int t = threadIdx.x;
    if (id >= 5888){
        // nlm1_w (32 m, 32 h, 1024 d) -> 4 rotated copies [rr][d][h][m_phys]
        // thread per (d,h); consecutive threads = consecutive d -> coalesced reads;
        // each rotation emitted as 16 contiguous u32 stores (64B, full sectors).
        int g = (id - 5888)*256 + t;            // 0..32767
        int h = g >> 10;
        int d = g & 1023;
        float vals[32];
        #pragma unroll
        for (int m=0;m<32;m++)
            vals[m] = wn[((size_t)m*32 + h)*1024 + d];
        unsigned short hi[32], lo[32];
        #pragma unroll
        for (int m=0;m<32;m++) split1(vals[m], hi[m], lo[m]);
        #pragma unroll
        for (int rr=0; rr<4; rr++){
            const int rot = rr + 1;
            unsigned wh[16], wl[16];
            #pragma unroll
            for (int i=0;i<16;i++){
                int s0 = (2*i   - rot) & 31;
                int s1 = (2*i+1 - rot) & 31;
                wh[i] = (unsigned)hi[s0] | ((unsigned)hi[s1] << 16);
                wl[i] = (unsigned)lo[s0] | ((unsigned)lo[s1] << 16);
            }
            size_t o = ((size_t)d*1024 + (size_t)h*32) >> 1;  // u32 units
            unsigned* dh = (unsigned*)g_w1rH[rr] + o;
            unsigned* dl = (unsigned*)g_w1rL[rr] + o;
            #pragma unroll
            for (int i=0;i<16;i++){ dh[i] = wh[i]; dl[i] = wl[i]; }
        }
        return;
    }
    __shared__ float sm[32][33];
    const float* W; unsigned *Th, *Tl; int K, N; int local;
    if (id < 256)      { W=w0; Th=g_w1H; Tl=g_w1L; K=256;  N=1024; local=id; }
    else if (id < 768) { W=w1; Th=g_w2H; Tl=g_w2L; K=512;  N=1024; local=id-256; }
    else if (id < 3840){ W=w2; Th=g_s1H; Tl=g_s1L; K=1536; N=2048; local=id-768; }
    else               { W=w3; Th=g_s2H; Tl=g_s2L; K=1024; N=2048; local=id-3840; }
    int tx = N >> 5;
    int k0 = (local / tx)*32, n0 = (local % tx)*32;
    int r = t >> 3, c = (t & 7)*4;
    float4 v = *(const float4*)(W + (size_t)(k0+r)*N + n0 + c);
    sm[r][c] = v.x; sm[r][c+1] = v.y; sm[r][c+2] = v.z; sm[r][c+3] = v.w;
    __syncthreads();
    int nr = t >> 3, kp2 = (t & 7)*2;
    int kk = kp2*2;
    unsigned h0,l0,h1,l1;
    split2(sm[kk][nr],   sm[kk+1][nr], h0, l0);
    split2(sm[kk+2][nr], sm[kk+3][nr], h1, l1);
    int KP = K >> 1;
    size_t o = (size_t)(n0+nr)*KP + (k0>>1) + kp2;
    Th[o] = h0; Th[o+1] = h1;
    Tl[o] = l0; Tl[o+1] = l1;
}

// ---------------- 3xBF16 tensor GEMM, split-K, 64x64 tile, 256 thr, 4-stage --------------
#define GKP 12
__global__ __launch_bounds__(256) void gemm_bf16p(
    const unsigned* __restrict__ A1h, const unsigned* __restrict__ A1l, int lda1,
    const unsigned* __restrict__ A2h, const unsigned* __restrict__ A2l, int lda2, int KP1,
    const unsigned* __restrict__ Bh,  const unsigned* __restrict__ Bl,  int ldb,
    const float* __restrict__ bias, float* __restrict__ C, int N, int KPsplit)
{
    __shared__ unsigned As[4][2][64][GKP];
    __shared__ unsigned Bs[4][2][64][GKP];
    int tid = threadIdx.x;
    int m0 = blockIdx.y*64, n0 = blockIdx.x*64;
    int kbase = blockIdx.z * KPsplit;
    unsigned aBase = (unsigned)__cvta_generic_to_shared(&As[0][0][0][0]);
    unsigned bBase = (unsigned)__cvta_generic_to_shared(&Bs[0][0][0][0]);

    bool isB = tid >= 128;
    int lt = tid & 127;
    int lrow = lt >> 1, lch = lt & 1;
    int KT = KPsplit >> 3;

    int wid = tid >> 5, lane = tid & 31;
    int wm = wid >> 2, wn = wid & 3;
    int arow = wm*32 + (lane & 7) + (lane & 8);
    int akp  = (lane & 16) ? 4 : 0;
    int brow = wn*16 + (lane & 7) + ((lane & 16) ? 8 : 0);
    int bkp  = (lane & 8) ? 4 : 0;
    unsigned aOff0 = ((unsigned)(arow     *GKP + akp))*4u;
    unsigned aOff1 = ((unsigned)((arow+16)*GKP + akp))*4u;
    unsigned bOff  = ((unsigned)(brow     *GKP + bkp))*4u;

    float acc[2][2][4];
    #pragma unroll
    for (int a=0;a<2;a++)
        #pragma unroll
        for (int b=0;b<2;b++)
            #pragma unroll
            for (int c=0;c<4;c++) acc[a][b][c]=0.f;

    auto issue = [&](int kt){
        if (kt < KT){
            int st = kt & 3;
            int kp0 = kbase + kt*8 + lch*4;
            unsigned dh = (((unsigned)(st*2+0)*64 + lrow)*GKP + lch*4)*4u;
            unsigned dl = (((unsigned)(st*2+1)*64 + lrow)*GKP + lch*4)*4u;
            if (!isB){
                const unsigned *sh_, *sl_;
                if (kp0 < KP1){
                    size_t o = (size_t)(m0+lrow)*lda1 + kp0;
                    sh_ = A1h + o; sl_ = A1l + o;
                } else {
                    size_t o = (size_t)(m0+lrow)*lda2 + (kp0 - KP1);
                    sh_ = A2h + o; sl_ = A2l + o;
                }
                cpasync16(aBase + dh, sh_);
                cpasync16(aBase + dl, sl_);
            } else {
                size_t o = (size_t)(n0+lrow)*ldb + kp0;
                cpasync16(bBase + dh, Bh + o);
                cpasync16(bBase + dl, Bl + o);
            }
        }
        asm volatile("cp.async.commit_group;" ::: "memory");
    };

    issue(0); issue(1); issue(2);

    for (int kt = 0; kt < KT; kt++){
        asm volatile("cp.async.wait_group 2;" ::: "memory");
        __syncthreads();
        int st = kt & 3;
        unsigned sa = aBase + (unsigned)st*(2*64*GKP*4);
        unsigned sb = bBase + (unsigned)st*(2*64*GKP*4);
        unsigned ah0[4], ah1[4], al0[4], al1[4], bh[4], bl[4];
        ldsm4(ah0, sa + aOff0);
        ldsm4(ah1, sa + aOff1);
        ldsm4(al0, sa + (64*GKP*4) + aOff0);
        ldsm4(al1, sa + (64*GKP*4) + aOff1);
        ldsm4(bh,  sb + bOff);
        ldsm4(bl,  sb + (64*GKP*4) + bOff);

        mma16816(acc[0][0], ah0, bh+0);
        mma16816(acc[0][1], ah0, bh+2);
        mma16816(acc[1][0], ah1, bh+0);
        mma16816(acc[1][1], ah1, bh+2);
        mma16816(acc[0][0], ah0, bl+0);
        mma16816(acc[0][1], ah0, bl+2);
        mma16816(acc[1][0], ah1, bl+0);
        mma16816(acc[1][1], ah1, bl+2);
        mma16816(acc[0][0], al0, bh+0);
        mma16816(acc[0][1], al0, bh+2);
        mma16816(acc[1][0], al1, bh+0);
        mma16816(acc[1][1], al1, bh+2);

        issue(kt+3);
    }

    float* Cz = C + (size_t)blockIdx.z * (size_t)BB * (size_t)N;
    int g = lane >> 2, t4 = lane & 3;
    bool addb = (blockIdx.z == 0);
    #pragma unroll
    for (int mt=0;mt<2;mt++){
        #pragma unroll
        for (int nt=0;nt<2;nt++){
            int row = m0 + wm*32 + mt*16 + g;
            int col = n0 + wn*16 + nt*8 + 2*t4;
            float bx = addb ? __ldg(bias + col)     : 0.f;
            float by = addb ? __ldg(bias + col + 1) : 0.f;
            float2 v0 = make_float2(acc[mt][nt][0]+bx, acc[mt][nt][1]+by);
            float2 v1 = make_float2(acc[mt][nt][2]+bx, acc[mt][nt][3]+by);
            *(float2*)&Cz[(size_t)row*N + col]     = v0;
            *(float2*)&Cz[(size_t)(row+8)*N + col] = v1;
        }
    }
}

// ---------------- GLU + LayerNorm (sums NP split-K partials) -> packed bf16 hi/lo ------
template<int NP>
__global__ __launch_bounds__(256) void glu_ln_pack(
    const float* __restrict__ X, const float* __restrict__ gamma,
    const float* __restrict__ beta, unsigned* __restrict__ outH,
    unsigned* __restrict__ outL, int N)
{
    __shared__ float sg[1024];
    __shared__ float red[18];
    int b = blockIdx.x, t = threadIdx.x;
    size_t zstride = (size_t)BB*2*N;
    const float* xr = X + (size_t)b*2*N;
    int N4 = N >> 2;
    float s1=0.f, s2=0.f;
    for (int p=t; p<N4; p+=256){
        float4 a = *(const float4*)(xr + 4*p);
        float4 c = *(const float4*)(xr + N + 4*p);
        #pragma unroll
        for (int z=1; z<NP; z++){
            float4 a2 = *(const float4*)(xr + z*zstride + 4*p);
            float4 c2 = *(const float4*)(xr + z*zstride + N + 4*p);
            a.x+=a2.x; a.y+=a2.y; a.z+=a2.z; a.w+=a2.w;
            c.x+=c2.x; c.y+=c2.y; c.z+=c2.z; c.w+=c2.w;
        }
        float g0 = a.x*fsig(c.x), g1 = a.y*fsig(c.y);
        float g2 = a.z*fsig(c.z), g3 = a.w*fsig(c.w);
        *(float4*)&sg[4*p] = make_float4(g0,g1,g2,g3);
        s1 += (g0+g1)+(g2+g3);
        s2 += (g0*g0+g1*g1)+(g2*g2+g3*g3);
    }
    #pragma unroll
    for (int o=16;o;o>>=1){ s1+=__shfl_xor_sync(0xffffffffu,s1,o); s2+=__shfl_xor_sync(0xffffffffu,s2,o); }
    if ((t&31)==0){ red[t>>5]=s1; red[8+(t>>5)]=s2; }
    __syncthreads();
    if (t==0){
        float a=0.f,c=0.f;
        for (int i=0;i<8;i++){ a+=red[i]; c+=red[8+i]; }
        red[16]=a; red[17]=c;
    }
    __syncthreads();
    float mu  = red[16]/(float)N;
    float var = red[17]/(float)N - mu*mu;
    float inv = rsqrtf(var + 1e-6f);
    int NP2 = N >> 1;
    for (int p=t; p<N4; p+=256){
        int j = 4*p;
        float4 gm = *(const float4*)(gamma + j);
        float4 bt = *(const float4*)(beta + j);
        float4 gv = *(const float4*)&sg[j];
        float y0 = (gv.x-mu)*inv*gm.x + bt.x;
        float y1 = (gv.y-mu)*inv*gm.y + bt.y;
        float y2 = (gv.z-mu)*inv*gm.z + bt.z;
        float y3 = (gv.w-mu)*inv*gm.w + bt.w;
        unsigned h0,l0,h1,l1;
        split2(y0,y1,h0,l0);
        split2(y2,y3,h1,l1);
        size_t o = (size_t)b*NP2 + 2*p;
        *(uint2*)&outH[o] = make_uint2(h0,h1);
        *(uint2*)&outL[o] = make_uint2(l0,l1);
    }
}

// ---------------- GLU + LayerNorm (sums NP partials) -> fp32 st slot + packed st slot --------
template<int NP>
__global__ __launch_bounds__(256) void glu_ln_f32(
    const float* __restrict__ X, const float* __restrict__ gamma,
    const float* __restrict__ beta, float* __restrict__ outp,
    int N, int ostride, int slot)
{
    __shared__ float sg[1024];
    __shared__ float red[18];
    int b = blockIdx.x, t = threadIdx.x;
    size_t zstride = (size_t)BB*2*N;
    const float* xr = X + (size_t)b*2*N;
    int N4 = N >> 2;
    float s1=0.f, s2=0.f;
    for (int p=t; p<N4; p+=256){
        float4 a = *(const float4*)(xr + 4*p);
        float4 c = *(const float4*)(xr + N + 4*p);
        #pragma unroll
        for (int z=1; z<NP; z++){
            float4 a2 = *(const float4*)(xr + z*zstride + 4*p);
            float4 c2 = *(const float4*)(xr + z*zstride + N + 4*p);
            a.x+=a2.x; a.y+=a2.y; a.z+=a2.z; a.w+=a2.w;
            c.x+=c2.x; c.y+=c2.y; c.z+=c2.z; c.w+=c2.w;
        }
        float g0 = a.x*fsig(c.x), g1 = a.y*fsig(c.y);
        float g2 = a.z*fsig(c.z), g3 = a.w*fsig(c.w);
        *(float4*)&sg[4*p] = make_float4(g0,g1,g2,g3);
        s1 += (g0+g1)+(g2+g3);
        s2 += (g0*g0+g1*g1)+(g2*g2+g3*g3);
    }
    #pragma unroll
    for (int o=16;o;o>>=1){ s1+=__shfl_xor_sync(0xffffffffu,s1,o); s2+=__shfl_xor_sync(0xffffffffu,s2,o); }
    if ((t&31)==0){ red[t>>5]=s1; red[8+(t>>5)]=s2; }
    __syncthreads();
    if (t==0){
        float a=0.f,c=0.f;
        for (int i=0;i<8;i++){ a+=red[i]; c+=red[8+i]; }
        red[16]=a; red[17]=c;
    }
    __syncthreads();
    float mu  = red[16]/(float)N;
    float var = red[17]/(float)N - mu*mu;
    float inv = rsqrtf(var + 1e-6f);
    for (int p=t; p<N4; p+=256){
        int j = 4*p;
        float4 gm = *(const float4*)(gamma + j);
        float4 bt = *(const float4*)(beta + j);
        float4 gv = *(const float4*)&sg[j];
        float4 y;
        y.x = (gv.x-mu)*inv*gm.x + bt.x;
        y.y = (gv.y-mu)*inv*gm.y + bt.y;
        y.z = (gv.z-mu)*inv*gm.z + bt.z;
        y.w = (gv.w-mu)*inv*gm.w + bt.w;
        *(float4*)&outp[(size_t)b*ostride + j] = y;
        #pragma unroll
        for (int q=0;q<4;q++){
            float v = (&y.x)[q];
            unsigned short hh, ll;
            split1(v, hh, ll);
            size_t po = (size_t)(j+q)*(256*32) + (size_t)b*32 + slot;
            g_stH16[po] = hh;
            g_stL16[po] = ll;
        }
    }
}

// ---------------- tensor-core NLM: per-d GEMM [128b x 32m] @ [32m x 32h] -----------------
__global__ __launch_bounds__(256) void nlm_tc(
    const float* __restrict__ b1, const float* __restrict__ T1,
    const float* __restrict__ w2, const float* __restrict__ b2, const float* __restrict__ T2,
    int it)
{
    __shared__ __align__(16) unsigned char sA[2][128*80];
    __shared__ __align__(16) unsigned char sW[2][32*80];
    __shared__ float B1s[32];
    __shared__ float W2s[32];
    __shared__ float B2s[2];
    __shared__ float Ts[2];

    int t = threadIdx.x;
    int b0 = blockIdx.x * 128;
    int d  = blockIdx.y;
    int slot = it;

    {
        int r = t >> 1, half = t & 1;
        size_t srcoff = ((size_t)d*256 + b0 + r)*64 + (size_t)half*32;
        const uint4* sh = (const uint4*)((const char*)g_stH16 + srcoff);
        const uint4* sl = (const uint4*)((const char*)g_stL16 + srcoff);
        uint4* dh = (uint4*)(sA[0] + r*80 + half*32);
        uint4* dl = (uint4*)(sA[1] + r*80 + half*32);
        dh[0] = sh[0]; dh[1] = sh[1];
        dl[0] = sl[0]; dl[1] = sl[1];
    }
    {
        int hl = t >> 7, tt = t & 127;
        int r = tt >> 2, part = (tt & 3)*16;
        const char* src = (const char*)(hl ? g_w1rL[it] : g_w1rH[it]) + (size_t)d*2048 + r*64 + part;
        *(uint4*)(sW[hl] + r*80 + part) = *(const uint4*)src;
    }
    if (t < 32)      B1s[t] = b1[d*32 + t];
    else if (t < 64) W2s[t-32] = w2[(t-32)*1024 + d];
    else if (t == 64){ B2s[0] = b2[d*2]; B2s[1] = b2[d*2+1];
                       Ts[0] = 1.f/T1[0]; Ts[1] = 1.f/T2[0]; }
    __syncthreads();

    int wid = t >> 5, lane = t & 31;
    unsigned a0Base = (unsigned)__cvta_generic_to_shared(sA[0]);
    unsigned a1Base = (unsigned)__cvta_generic_to_shared(sA[1]);
    unsigned w0Base = (unsigned)__cvta_generic_to_shared(sW[0]);
    unsigned w1Base = (unsigned)__cvta_generic_to_shared(sW[1]);
    unsigned aOff = (unsigned)((wid*16 + (lane & 15))*80 + (lane >> 4)*16);
    unsigned bOff = (unsigned)((((lane & 7) + ((lane & 16) ? 8 : 0))*80) + ((lane & 8) ? 16 : 0));

    float acc[4][4];
    #pragma unroll
    for (int i=0;i<4;i++)
        #pragma unroll
        for (int j=0;j<4;j++) acc[i][j]=0.f;

    #pragma unroll
    for (int ks=0; ks<2; ks++){
        unsigned kb = ks*32;
        unsigned aH[4], aL[4], bh0[4], bh1[4], bl0[4], bl1[4];
        ldsm4(aH, a0Base + aOff + kb);
        ldsm4(aL, a1Base + aOff + kb);
        ldsm4(bh0, w0Base + bOff + kb);
        ldsm4(bh1, w0Base + bOff + 16*80 + kb);
        ldsm4(bl0, w1Base + bOff + kb);
        ldsm4(bl1, w1Base + bOff + 16*80 + kb);
        mma16816(acc[0], aH, bh0+0);
        mma16816(acc[1], aH, bh0+2);
        mma16816(acc[2], aH, bh1+0);
        mma16816(acc[3], aH, bh1+2);
        mma16816(acc[0], aH, bl0+0);
        mma16816(acc[1], aH, bl0+2);
        mma16816(acc[2], aH, bl1+0);
        mma16816(acc[3], aH, bl1+2);
        mma16816(acc[0], aL, bh0+0);
        mma16816(acc[1], aL, bh0+2);
        mma16816(acc[2], aL, bh1+0);
        mma16816(acc[3], aL, bh1+2);
    }

    int g = lane >> 2, t4 = lane & 3;
    float invT1 = Ts[0], invT2 = Ts[1];
    #pragma unroll
    for (int nt=0; nt<4; nt++)
        #pragma unroll
        for (int c=0; c<4; c++){
            int h = nt*8 + 2*t4 + (c & 1);
            acc[nt][c] = (acc[nt][c] + B1s[h]) * invT1;
        }
    float y0[2], y1[2];
    #pragma unroll
    for (int r=0; r<2; r++){
        y0[r]=0.f; y1[r]=0.f;
        #pragma unroll
        for (int nt=0; nt<2; nt++)
            #pragma unroll
            for (int e=0; e<2; e++){
                int c = r*2+e;
                float gl = acc[nt][c] * fsig(acc[nt+2][c]);
                int hp = nt*8 + 2*t4 + e;
                y0[r] += gl * W2s[hp*2+0];
                y1[r] += gl * W2s[hp*2+1];
            }
    }
    #pragma unroll
    for (int off=1; off<4; off<<=1){
        y0[0] += __shfl_xor_sync(0xffffffffu, y0[0], off);
        y1[0] += __shfl_xor_sync(0xffffffffu, y1[0], off);
        y0[1] += __shfl_xor_sync(0xffffffffu, y0[1], off);
        y1[1] += __shfl_xor_sync(0xffffffffu, y1[1], off);
    }
    if (t4 == 0){
        #pragma unroll
        for (int r=0; r<2; r++){
            float ya = (y0[r] + B2s[0]) * invT2;
            float yb = (y1[r] + B2s[1]) * invT2;
            float outv = ya * fsig(yb);
            int bg = b0 + wid*16 + g + r*8;
            g_at[((size_t)bg*MMM + slot)*DDIM + d] = outv;
            unsigned short hh, ll;
            split1(outv, hh, ll);
            ((unsigned short*)g_atH)[(size_t)bg*1024 + d] = hh;
            ((unsigned short*)g_atL)[(size_t)bg*1024 + d] = ll;
        }
    }
}

// ---------------- synchronization output (Horner) ----------------
__global__ __launch_bounds__(256) void synch_kernel(float* __restrict__ outp, int base)
{
    __shared__ float S[32][64];
    int b = blockIdx.x, t = threadIdx.x;
    #pragma unroll
    for (int i=0;i<8;i++){
        int idx = t + i*256; int m = idx >> 6, n = idx & 63;
        S[m][n] = g_at[((size_t)b*MMM + ((base+m)&31))*DDIM + (DDIM-NSYN) + n];
    }
    __syncthreads();
    for (int p=t; p<NSYNCH; p+=256){
        int i=0, off=0;
        while (p >= off + (NSYN - i)){ off += NSYN - i; ++i; }
        int j = i + (p - off);
        float r = g_r[p];
        float num = 0.f;
        #pragma unroll
        for (int m=0;m<32;m++)
            num = num*r + S[m][i]*S[m][j];
        outp[(size_t)b*NSYNCH + p] = num * g_invden[p];
    }
}

// ---------------- final transpose [b][m][d] -> (B,D,M) ----------------
__global__ void transpose_out(float* __restrict__ outp, int base)
{
    __shared__ float tile[32][33];
    const float* src = blockIdx.z ? g_at : g_st;
    float* dst = outp + (size_t)blockIdx.z * (size_t)BB*DDIM*MMM;
    int b = blockIdx.y, d0 = blockIdx.x*32, t = threadIdx.x;
    #pragma unroll
    for (int i=0;i<4;i++){
        int idx = t + i*256; int m = idx >> 5, dd = idx & 31;
        tile[m][dd] = src[((size_t)b*MMM + ((base+m)&31))*DDIM + d0 + dd];
    }
    __syncthreads();
    #pragma unroll
    for (int i=0;i<4;i++){
        int idx = t + i*256; int dd = idx >> 5, m = idx & 31;
        dst[((size_t)b*DDIM + d0 + dd)*MMM + m] = tile[m][dd];
    }
}

// ---------------- host launch ----------------
extern "C" void kernel_launch(void* const* d_in, const int* in_sizes, int n_in,
                              void* d_out, int out_size)
{
    const float* obs          = (const float*)d_in[0];
    const unsigned char* dones= (const unsigned char*)d_in[1];
    const float* state_trace  = (const float*)d_in[3];
    const float* at_trace     = (const float*)d_in[4];
    const float* start_trace  = (const float*)d_in[5];
    const float* start_at     = (const float*)d_in[6];
    const float* bb_w1  = (const float*)d_in[7];
    const float* bb_b1  = (const float*)d_in[8];
    const float* bb_l1s = (const float*)d_in[9];
    const float* bb_l1b = (const float*)d_in[10];
    const float* bb_w2  = (const float*)d_in[11];
    const float* bb_b2  = (const float*)d_in[12];
    const float* bb_l2s = (const float*)d_in[13];
    const float* bb_l2b = (const float*)d_in[14];
    const float* syn_w1 = (const float*)d_in[15];
    const float* syn_b1 = (const float*)d_in[16];
    const float* syn_l1s= (const float*)d_in[17];
    const float* syn_l1b= (const float*)d_in[18];
    const float* syn_w2 = (const float*)d_in[19];
    const float* syn_b2 = (const float*)d_in[20];
    const float* syn_l2s= (const float*)d_in[21];
    const float* syn_l2b= (const float*)d_in[22];
    const float* nlm1_w = (const float*)d_in[23];
    const float* nlm1_b = (const float*)d_in[24];
    const float* nlm1_T = (const float*)d_in[25];
    const float* nlm2_w = (const float*)d_in[26];
    const float* nlm2_b = (const float*)d_in[27];
    const float* nlm2_T = (const float*)d_in[28];
    const float* decayp = (const float*)d_in[29];
    float* outp = (float*)d_out;

    float *p_tmp, *p_st;
    unsigned *p_obsH,*p_obsL,*p_fH,*p_fL,*p_hH,*p_hL,*p_atH,*p_atL;
    unsigned *p_w1H,*p_w1L,*p_w2H,*p_w2L,*p_s1H,*p_s1L,*p_s2H,*p_s2L;
    cudaGetSymbolAddress((void**)&p_tmp, g_tmp);
    cudaGetSymbolAddress((void**)&p_st,  g_st);
    cudaGetSymbolAddress((void**)&p_obsH, g_obsH); cudaGetSymbolAddress((void**)&p_obsL, g_obsL);
    cudaGetSymbolAddress((void**)&p_fH,   g_fH);   cudaGetSymbolAddress((void**)&p_fL,   g_fL);
    cudaGetSymbolAddress((void**)&p_hH,   g_hH);   cudaGetSymbolAddress((void**)&p_hL,   g_hL);
    cudaGetSymbolAddress((void**)&p_atH,  g_atH);  cudaGetSymbolAddress((void**)&p_atL,  g_atL);
    cudaGetSymbolAddress((void**)&p_w1H,  g_w1H);  cudaGetSymbolAddress((void**)&p_w1L,  g_w1L);
    cudaGetSymbolAddress((void**)&p_w2H,  g_w2H);  cudaGetSymbolAddress((void**)&p_w2L,  g_w2L);
    cudaGetSymbolAddress((void**)&p_s1H,  g_s1H);  cudaGetSymbolAddress((void**)&p_s1L,  g_s1L);
    cudaGetSymbolAddress((void**)&p_s2H,  g_s2H);  cudaGetSymbolAddress((void**)&p_s2L,  g_s2L);

    // 1) fused prep, state relayout (+packed st/at), weight conversion (+nlm1 rotations)
    prep_kernel<<<138, 256>>>(dones, decayp, obs);
    init_state<<<dim3(DDIM/32, BB), 256>>>(state_trace, at_trace, start_trace, start_at);
    conv_wt_all<<<6016, 256>>>(bb_w1, bb_w2, syn_w1, syn_w2, nlm1_w);

    // 2) backbone (split-K=2)
    gemm_bf16p<<<dim3(16, 4, 2), 256>>>(p_obsH, p_obsL, 128,
                                        p_obsH, p_obsL, 128, 128,
                                        p_w1H, p_w1L, 128,
                                        bb_b1, p_tmp, 1024, 64);
    glu_ln_pack<2><<<BB, 256>>>(p_tmp, bb_l1s, bb_l1b, p_fH, p_fL, DIN);
    gemm_bf16p<<<dim3(16, 4, 2), 256>>>(p_fH, p_fL, 256,
                                        p_fH, p_fL, 256, 256,
                                        p_w2H, p_w2L, 256,
                                        bb_b2, p_tmp, 1024, 128);
    glu_ln_pack<2><<<BB, 256>>>(p_tmp, bb_l2s, bb_l2b, p_fH, p_fL, DIN);

    // 3) recurrent iterations (split-K=4 on syn GEMMs, tensor-core NLM)
    for (int t = 0; t < NITR; t++){
        gemm_bf16p<<<dim3(32, 4, 4), 256>>>(p_fH, p_fL, 256,
                                            p_atH, p_atL, 512, 256,
                                            p_s1H, p_s1L, 768,
                                            syn_b1, p_tmp, 2048, 192);
        glu_ln_pack<4><<<BB, 256>>>(p_tmp, syn_l1s, syn_l1b, p_hH, p_hL, DDIM);
        gemm_bf16p<<<dim3(32, 4, 4), 256>>>(p_hH, p_hL, 512,
                                            p_hH, p_hL, 512, 512,
                                            p_s2H, p_s2L, 512,
                                            syn_b2, p_tmp, 2048, 128);
        glu_ln_f32<4><<<BB, 256>>>(p_tmp, syn_l2s, syn_l2b, p_st + (size_t)t*DDIM,
                                   DDIM, MMM*DDIM, t);
        nlm_tc<<<dim3(2, 1024), 256>>>(nlm1_b, nlm1_T, nlm2_w, nlm2_b, nlm2_T, t);
    }

    // 4) outputs
    synch_kernel<<<BB, 256>>>(outp + (size_t)2*BB*DDIM*MMM, NITR & 31);
    transpose_out<<<dim3(DDIM/32, BB, 2), 256>>>(outp, NITR & 31);
}